// round 12
// baseline (speedup 1.0000x reference)
#include <cuda_runtime.h>
#include <cstdint>
#include <cstdio>

#define SEQ_LEN 2048
#define BATCHSZ 32
#define HIDDEN  512
#define VOCAB   32000
#define GWID    2048   /* 4*HIDDEN */
#define NCTA    128    /* 64 CTAs per direction */

// ---------------- device scratch (static allocation: allowed) ----------------
__device__ float    g_table[(size_t)2 * VOCAB * GWID];   // 524 MB: per-vocab gate bias table
__device__ float    g_hbuf[2][2][HIDDEN * BATCHSZ];      // [dir][phase][k*32+b]
__device__ unsigned g_bar[SEQ_LEN];                      // per-step grid-barrier counters
__device__ int      g_tok64;                             // tokens are int64 (1) or int32 (0)

// ---------------- init: zero barriers, seed h, detect token width ------------
__global__ void init_kernel(const int* __restrict__ tok32, const float* __restrict__ h0) {
    int i = blockIdx.x * blockDim.x + threadIdx.x;
    if (i < SEQ_LEN) g_bar[i] = 0;
    if (i < 2 * HIDDEN * BATCHSZ) {
        int d  = i >> 14;           // dir
        int rb = i & 16383;         // r*32+b
        int b  = rb & 31;
        int r  = rb >> 5;
        g_hbuf[d][0][rb] = h0[b * HIDDEN + r];
    }
    if (i == 0) {
        // If tokens are int64, every odd int32 word (high half) is 0.
        int nz = 0;
        for (int j = 0; j < 128; ++j) nz |= tok32[2 * j + 1];
        g_tok64 = (nz == 0) ? 1 : 0;
    }
}

// ---------------- vocab gate-table GEMM: table[d][v][c] = E[v]@Wx + bx + bh ---
// Tile: 128 (v) x 64 (c), K-chunk 16, 256 threads, 8x4 microtile.
__global__ void __launch_bounds__(256) gx_gemm_kernel(
    const float* __restrict__ E,
    const float* __restrict__ wx_f, const float* __restrict__ bx_f, const float* __restrict__ bh_f,
    const float* __restrict__ wx_b, const float* __restrict__ bx_b, const float* __restrict__ bh_b)
{
    const int d  = blockIdx.z;
    const float* Wx = d ? wx_b : wx_f;
    const float* bx = d ? bx_b : bx_f;
    const float* bh = d ? bh_b : bh_f;
    const int c0 = blockIdx.x * 64;
    const int v0 = blockIdx.y * 128;

    __shared__ float As[16][132];   // [k][row], padded
    __shared__ float Bs[16][64];    // [k][c]

    const int tid = threadIdx.x;
    const int tx  = tid & 15;       // 0..15 -> 4 cols each
    const int ty  = tid >> 4;       // 0..15 -> 8 rows each

    float acc[8][4];
#pragma unroll
    for (int i = 0; i < 8; ++i)
#pragma unroll
        for (int j = 0; j < 4; ++j) acc[i][j] = 0.0f;

    const int arow = tid >> 2;      // 0..63
    const int akq  = tid & 3;       // 0..3
    const int bk   = tid >> 4;      // 0..15
    const int bcq  = tid & 15;      // 0..15

    for (int kk = 0; kk < HIDDEN; kk += 16) {
#pragma unroll
        for (int p = 0; p < 2; ++p) {
            int rr = arow + p * 64;
            float4 e = *(const float4*)(E + (size_t)(v0 + rr) * HIDDEN + kk + akq * 4);
            As[akq * 4 + 0][rr] = e.x;
            As[akq * 4 + 1][rr] = e.y;
            As[akq * 4 + 2][rr] = e.z;
            As[akq * 4 + 3][rr] = e.w;
        }
        float4 wv = *(const float4*)(Wx + (size_t)(kk + bk) * GWID + c0 + bcq * 4);
        *(float4*)&Bs[bk][bcq * 4] = wv;
        __syncthreads();

#pragma unroll
        for (int k = 0; k < 16; ++k) {
            float a[8], b4[4];
            *(float4*)&a[0] = *(const float4*)&As[k][ty * 8];
            *(float4*)&a[4] = *(const float4*)&As[k][ty * 8 + 4];
            *(float4*)&b4[0] = *(const float4*)&Bs[k][tx * 4];
#pragma unroll
            for (int i = 0; i < 8; ++i)
#pragma unroll
                for (int j = 0; j < 4; ++j) acc[i][j] += a[i] * b4[j];
        }
        __syncthreads();
    }

    float4 bxv = *(const float4*)(bx + c0 + tx * 4);
    float4 bhv = *(const float4*)(bh + c0 + tx * 4);
    float bias[4] = { bxv.x + bhv.x, bxv.y + bhv.y, bxv.z + bhv.z, bxv.w + bhv.w };

    float* Cbase = g_table + (size_t)d * VOCAB * GWID;
#pragma unroll
    for (int i = 0; i < 8; ++i) {
        float4 o;
        o.x = acc[i][0] + bias[0];
        o.y = acc[i][1] + bias[1];
        o.z = acc[i][2] + bias[2];
        o.w = acc[i][3] + bias[3];
        *(float4*)(Cbase + (size_t)(v0 + ty * 8 + i) * GWID + c0 + tx * 4) = o;
    }
}

// ---------------- persistent bidirectional LSTM recurrence -------------------
// 128 CTAs x 128 threads. CTA owns dir = blockIdx.x>>6, hidden units K0..K0+7.
// SMEM: wh slice [512][32] + h stage [512][32] + reduce/gate/cell buffers.
#define SM_WS   0
#define SM_HS   16384
#define SM_RED  32768                 /* [4][32][36] */
#define SM_GB   (SM_RED + 4*32*36)    /* [32][36]   */
#define SM_CS   (SM_GB + 32*36)       /* [8][33]    */
#define SM_HOUT (SM_CS + 8*33)        /* [32][8]    */
#define SM_FLOATS (SM_HOUT + 32*8)    /* 39048 floats = 156192 B */

__global__ void __launch_bounds__(128, 1) rnn_kernel(
    const void* __restrict__ tokens_raw,
    const float* __restrict__ h0,
    const float* __restrict__ wh_f,
    const float* __restrict__ wh_b,
    float* __restrict__ out)
{
    extern __shared__ float smem[];
    float* ws   = smem + SM_WS;
    float* hs   = smem + SM_HS;
    float* red  = smem + SM_RED;
    float* gbuf = smem + SM_GB;
    float* cs   = smem + SM_CS;
    float* hout = smem + SM_HOUT;

    const int tid = threadIdx.x;
    const int dir = blockIdx.x >> 6;
    const int K0  = (blockIdx.x & 63) * 8;
    const float* wh = dir ? wh_b : wh_f;

    // Load this CTA's wh slice: ws[r*32 + g*8 + j] = wh[r][g*512 + K0 + j]
    for (int i = tid; i < 16384; i += 128) {
        int r = i >> 5, c = i & 31;
        int g = c >> 3, j = c & 7;
        ws[i] = wh[(size_t)r * GWID + g * HIDDEN + K0 + j];
    }
    // Init cell state: c0 = h0 (reference uses (h0, h0) as carry)
#pragma unroll
    for (int rep = 0; rep < 2; ++rep) {
        int id = tid + rep * 128;
        int j = id >> 5, b = id & 31;
        cs[j * 33 + b] = h0[b * HIDDEN + K0 + j];
    }
    __syncthreads();

    const int tok64 = g_tok64;
    const float* table = g_table + (size_t)dir * VOCAB * GWID;
    float* hb0 = &g_hbuf[dir][0][0];
    float* hb1 = &g_hbuf[dir][1][0];

    const int w  = tid >> 5, l = tid & 31;   // warp, lane
    const int bg = l & 3,  cg = l >> 2;      // batch-group(8), col-group(4)
    const int gb = tid >> 2, gq = tid & 3;   // reduce: batch, gate chunk

    int buf = 0;
    for (int s = 0; s < SEQ_LEN; ++s) {
        const int t = dir ? (SEQ_LEN - 1 - s) : s;

        // ---- gx prefetch (independent of the barrier): this thread later
        //      reduces (b=gb, cols gq*8..gq*8+7) -> load matching table chunk.
        long long tok;
        if (tok64) tok = ((const long long*)tokens_raw)[(size_t)t * BATCHSZ + gb];
        else       tok = (long long)((const int*)tokens_raw)[(size_t)t * BATCHSZ + gb];
        const float* gp = table + (size_t)tok * GWID + gq * HIDDEN + K0;
        float4 gx0 = *(const float4*)gp;
        float4 gx1 = *(const float4*)(gp + 4);

        // ---- grid barrier: all CTAs finished writing h(s-1)
        __syncthreads();
        if (tid == 0) {
            __threadfence();
            atomicAdd(&g_bar[s], 1u);
            while (*(volatile unsigned*)&g_bar[s] < (unsigned)gridDim.x) { }
            __threadfence();
        }
        __syncthreads();

        // ---- stage h (this warp's 128 r-rows) via L2 (other SMs wrote it)
        {
            const float4* src = (const float4*)(buf ? hb1 : hb0) + w * 1024;
            float4* dst = (float4*)hs + w * 1024;
#pragma unroll
            for (int i = 0; i < 32; ++i)
                dst[i * 32 + l] = __ldcg(src + i * 32 + l);
        }
        __syncwarp();

        // ---- FMA: acc[b_i][c_j] over this warp's 128 r
        float acc[8][4];
#pragma unroll
        for (int i = 0; i < 8; ++i)
#pragma unroll
            for (int j = 0; j < 4; ++j) acc[i][j] = 0.0f;
        {
            const float* hrow = hs + (w << 12) + bg * 8;
            const float* wrow = ws + (w << 12) + cg * 4;
#pragma unroll 4
            for (int r = 0; r < 128; ++r) {
                float4 ha = *(const float4*)(hrow);
                float4 hb = *(const float4*)(hrow + 4);
                float4 wv = *(const float4*)(wrow);
                float hv[8] = { ha.x, ha.y, ha.z, ha.w, hb.x, hb.y, hb.z, hb.w };
                float wf[4] = { wv.x, wv.y, wv.z, wv.w };
#pragma unroll
                for (int i = 0; i < 8; ++i)
#pragma unroll
                    for (int j = 0; j < 4; ++j) acc[i][j] += hv[i] * wf[j];
                hrow += 32; wrow += 32;
            }
        }
        // ---- store partials: red[w][b][c]
#pragma unroll
        for (int i = 0; i < 8; ++i) {
            float4 v = make_float4(acc[i][0], acc[i][1], acc[i][2], acc[i][3]);
            *(float4*)(red + ((w * 32 + bg * 8 + i) * 36 + cg * 4)) = v;
        }
        __syncthreads();

        // ---- reduce 4 warps + gx -> gates
        {
            float gx[8] = { gx0.x, gx0.y, gx0.z, gx0.w, gx1.x, gx1.y, gx1.z, gx1.w };
#pragma unroll
            for (int cc = 0; cc < 8; ++cc) {
                int c = gq * 8 + cc;
                float v = red[(0 * 32 + gb) * 36 + c] + red[(1 * 32 + gb) * 36 + c]
                        + red[(2 * 32 + gb) * 36 + c] + red[(3 * 32 + gb) * 36 + c]
                        + gx[cc];
                gbuf[gb * 36 + c] = v;
            }
        }
        __syncthreads();

        // ---- LSTM cell (256 cells, 2 per thread), write h to other phase buf
        float* hdst = buf ? hb0 : hb1;
#pragma unroll
        for (int rep = 0; rep < 2; ++rep) {
            int id = tid + rep * 128;
            int j = id >> 5, b = id & 31;
            float ig = gbuf[b * 36 + j];
            float fg = gbuf[b * 36 + 8 + j];
            float gg = gbuf[b * 36 + 16 + j];
            float og = gbuf[b * 36 + 24 + j];
            float iv = 1.0f / (1.0f + __expf(-ig));
            float fv = 1.0f / (1.0f + __expf(-fg));
            float ov = 1.0f / (1.0f + __expf(-og));
            float gv = tanhf(gg);
            float c2 = fv * cs[j * 33 + b] + iv * gv;
            cs[j * 33 + b] = c2;
            float h2 = ov * tanhf(c2);
            hdst[(K0 + j) * BATCHSZ + b] = h2;     // coalesced over b
            hout[b * 8 + j] = h2;
        }
        __syncthreads();

        // ---- output write: out[b][t*1024 + dir*512 + K0 + 0..7]
        if (tid < 64) {
            int b = tid >> 1, half = tid & 1;
            float4 v = *(float4*)(hout + b * 8 + half * 4);
            *(float4*)(out + (size_t)b * (SEQ_LEN * 1024)
                           + (size_t)t * 1024 + dir * 512 + K0 + half * 4) = v;
        }
        buf ^= 1;
    }
}

// ---------------- launch ------------------------------------------------------
extern "C" void kernel_launch(void* const* d_in, const int* in_sizes, int n_in,
                              void* d_out, int out_size)
{
    const void*  tokens = d_in[0];
    const float* h0     = (const float*)d_in[1];
    const float* emb    = (const float*)d_in[2];
    const float* wx_f   = (const float*)d_in[3];
    const float* bx_f   = (const float*)d_in[4];
    const float* wh_f   = (const float*)d_in[5];
    const float* bh_f   = (const float*)d_in[6];
    const float* wx_b   = (const float*)d_in[7];
    const float* bx_b   = (const float*)d_in[8];
    const float* wh_b   = (const float*)d_in[9];
    const float* bh_b   = (const float*)d_in[10];
    float* out = (float*)d_out;

    cudaFuncSetAttribute(rnn_kernel, cudaFuncAttributeMaxDynamicSharedMemorySize,
                         SM_FLOATS * (int)sizeof(float));

    // 1) vocab gate table (parallel GEMM)
    dim3 gg(GWID / 64, VOCAB / 128, 2);
    gx_gemm_kernel<<<gg, 256>>>(emb, wx_f, bx_f, bh_f, wx_b, bx_b, bh_b);

    // 2) reset barriers, seed h, detect token dtype
    init_kernel<<<128, 256>>>((const int*)tokens, h0);

    // 3) persistent recurrence (both directions concurrently)
    rnn_kernel<<<NCTA, 128, SM_FLOATS * (int)sizeof(float)>>>(
        tokens, h0, wh_f, wh_b, out);
}

// round 13
// speedup vs baseline: 1.0134x; 1.0134x over previous
#include <cuda_runtime.h>
#include <cstdint>
#include <cstdio>

#define SEQ_LEN 2048
#define BATCHSZ 32
#define HIDDEN  512
#define VOCAB   32000
#define GWID    2048   /* 4*HIDDEN */
#define NCTA    128    /* 64 CTAs per direction */

typedef unsigned long long u64;

// packed fp32x2 FMA (sm_100+): d = a*b + c on both lanes
#define FMA2(d, a, b, c) \
    asm("fma.rn.f32x2 %0, %1, %2, %3;" : "=l"(d) : "l"(a), "l"(b), "l"(c))
// splat one float into both halves of a 64-bit pair
#define SPLAT2(d, f) \
    asm("mov.b64 %0, {%1, %1};" : "=l"(d) : "f"(f))
// unpack
#define UNPK2(lo, hi, d) \
    asm("mov.b64 {%0, %1}, %2;" : "=f"(lo), "=f"(hi) : "l"(d))

// ---------------- device scratch (static allocation: allowed) ----------------
__device__ float    g_table[(size_t)2 * VOCAB * GWID];   // 524 MB: per-vocab gate bias table
__device__ float    g_hbuf[2][2][HIDDEN * BATCHSZ];      // [dir][phase][k*32+b]
__device__ unsigned g_bar[SEQ_LEN];                      // per-step grid-barrier counters
__device__ int      g_tok64;                             // tokens are int64 (1) or int32 (0)

// ---------------- init: zero barriers, seed h, detect token width ------------
__global__ void init_kernel(const int* __restrict__ tok32, const float* __restrict__ h0) {
    int i = blockIdx.x * blockDim.x + threadIdx.x;
    if (i < SEQ_LEN) g_bar[i] = 0;
    if (i < 2 * HIDDEN * BATCHSZ) {
        int d  = i >> 14;           // dir
        int rb = i & 16383;         // r*32+b
        int b  = rb & 31;
        int r  = rb >> 5;
        g_hbuf[d][0][rb] = h0[b * HIDDEN + r];
    }
    if (i == 0) {
        // If tokens are int64, every odd int32 word (high half) is 0.
        int nz = 0;
        for (int j = 0; j < 128; ++j) nz |= tok32[2 * j + 1];
        g_tok64 = (nz == 0) ? 1 : 0;
    }
}

// ---------------- vocab gate-table GEMM: table[d][v][c] = E[v]@Wx + bx + bh ---
// Tile: 128 (v) x 64 (c), K-chunk 16, 256 threads, 8x4 microtile, FFMA2 core.
__global__ void __launch_bounds__(256) gx_gemm_kernel(
    const float* __restrict__ E,
    const float* __restrict__ wx_f, const float* __restrict__ bx_f, const float* __restrict__ bh_f,
    const float* __restrict__ wx_b, const float* __restrict__ bx_b, const float* __restrict__ bh_b)
{
    const int d  = blockIdx.z;
    const float* Wx = d ? wx_b : wx_f;
    const float* bx = d ? bx_b : bx_f;
    const float* bh = d ? bh_b : bh_f;
    const int c0 = blockIdx.x * 64;
    const int v0 = blockIdx.y * 128;

    __shared__ float As[16][132];   // [k][row], padded (132 even -> 8B-aligned pairs)
    __shared__ float Bs[16][64];    // [k][c]

    const int tid = threadIdx.x;
    const int tx  = tid & 15;       // 0..15 -> 4 cols each
    const int ty  = tid >> 4;       // 0..15 -> 8 rows each

    u64 acc2[4][4];
#pragma unroll
    for (int i = 0; i < 4; ++i)
#pragma unroll
        for (int j = 0; j < 4; ++j) acc2[i][j] = 0ull;

    const int arow = tid >> 2;      // 0..63
    const int akq  = tid & 3;       // 0..3
    const int bk   = tid >> 4;      // 0..15
    const int bcq  = tid & 15;      // 0..15

    for (int kk = 0; kk < HIDDEN; kk += 16) {
#pragma unroll
        for (int p = 0; p < 2; ++p) {
            int rr = arow + p * 64;
            float4 e = *(const float4*)(E + (size_t)(v0 + rr) * HIDDEN + kk + akq * 4);
            As[akq * 4 + 0][rr] = e.x;
            As[akq * 4 + 1][rr] = e.y;
            As[akq * 4 + 2][rr] = e.z;
            As[akq * 4 + 3][rr] = e.w;
        }
        float4 wv = *(const float4*)(Wx + (size_t)(kk + bk) * GWID + c0 + bcq * 4);
        *(float4*)&Bs[bk][bcq * 4] = wv;
        __syncthreads();

#pragma unroll
        for (int k = 0; k < 16; ++k) {
            const float* arow_p = &As[k][ty * 8];
            u64 ap[4];
            ap[0] = *(const u64*)(arow_p + 0);
            ap[1] = *(const u64*)(arow_p + 2);
            ap[2] = *(const u64*)(arow_p + 4);
            ap[3] = *(const u64*)(arow_p + 6);
            float4 b4 = *(const float4*)&Bs[k][tx * 4];
            u64 w2[4];
            SPLAT2(w2[0], b4.x); SPLAT2(w2[1], b4.y);
            SPLAT2(w2[2], b4.z); SPLAT2(w2[3], b4.w);
#pragma unroll
            for (int p = 0; p < 4; ++p)
#pragma unroll
                for (int j = 0; j < 4; ++j)
                    FMA2(acc2[p][j], ap[p], w2[j], acc2[p][j]);
        }
        __syncthreads();
    }

    float4 bxv = *(const float4*)(bx + c0 + tx * 4);
    float4 bhv = *(const float4*)(bh + c0 + tx * 4);
    float bias[4] = { bxv.x + bhv.x, bxv.y + bhv.y, bxv.z + bhv.z, bxv.w + bhv.w };

    float* Cbase = g_table + (size_t)d * VOCAB * GWID;
#pragma unroll
    for (int p = 0; p < 4; ++p) {
        float lo[4], hi[4];
#pragma unroll
        for (int j = 0; j < 4; ++j) UNPK2(lo[j], hi[j], acc2[p][j]);
        float4 o0, o1;
        o0.x = lo[0] + bias[0]; o0.y = lo[1] + bias[1];
        o0.z = lo[2] + bias[2]; o0.w = lo[3] + bias[3];
        o1.x = hi[0] + bias[0]; o1.y = hi[1] + bias[1];
        o1.z = hi[2] + bias[2]; o1.w = hi[3] + bias[3];
        *(float4*)(Cbase + (size_t)(v0 + ty * 8 + 2 * p)     * GWID + c0 + tx * 4) = o0;
        *(float4*)(Cbase + (size_t)(v0 + ty * 8 + 2 * p + 1) * GWID + c0 + tx * 4) = o1;
    }
}

// ---------------- persistent bidirectional LSTM recurrence -------------------
// 128 CTAs x 128 threads. CTA owns dir = blockIdx.x>>6, hidden units K0..K0+7.
// SMEM: wh slice [512][32] + h stage [512][32] + reduce/gate/cell buffers.
#define SM_WS   0
#define SM_HS   16384
#define SM_RED  32768                 /* [4][32][36] */
#define SM_GB   (SM_RED + 4*32*36)    /* [32][36]   */
#define SM_CS   (SM_GB + 32*36)       /* [8][33]    */
#define SM_HOUT (SM_CS + 8*33)        /* [32][8]    */
#define SM_FLOATS (SM_HOUT + 32*8)    /* 39048 floats = 156192 B */

__global__ void __launch_bounds__(128, 1) rnn_kernel(
    const void* __restrict__ tokens_raw,
    const float* __restrict__ h0,
    const float* __restrict__ wh_f,
    const float* __restrict__ wh_b,
    float* __restrict__ out)
{
    extern __shared__ float smem[];
    float* ws   = smem + SM_WS;
    float* hs   = smem + SM_HS;
    float* red  = smem + SM_RED;
    float* gbuf = smem + SM_GB;
    float* cs   = smem + SM_CS;
    float* hout = smem + SM_HOUT;

    const int tid = threadIdx.x;
    const int dir = blockIdx.x >> 6;
    const int K0  = (blockIdx.x & 63) * 8;
    const float* wh = dir ? wh_b : wh_f;

    // Load this CTA's wh slice: ws[r*32 + g*8 + j] = wh[r][g*512 + K0 + j]
    for (int i = tid; i < 16384; i += 128) {
        int r = i >> 5, c = i & 31;
        int g = c >> 3, j = c & 7;
        ws[i] = wh[(size_t)r * GWID + g * HIDDEN + K0 + j];
    }
    // Init cell state: c0 = h0 (reference uses (h0, h0) as carry)
#pragma unroll
    for (int rep = 0; rep < 2; ++rep) {
        int id = tid + rep * 128;
        int j = id >> 5, b = id & 31;
        cs[j * 33 + b] = h0[b * HIDDEN + K0 + j];
    }
    __syncthreads();

    const int tok64 = g_tok64;
    const float* table = g_table + (size_t)dir * VOCAB * GWID;
    float* hb0 = &g_hbuf[dir][0][0];
    float* hb1 = &g_hbuf[dir][1][0];

    const int w  = tid >> 5, l = tid & 31;   // warp, lane
    const int bg = l & 3,  cg = l >> 2;      // batch-group(8), col-group(4)
    const int gb = tid >> 2, gq = tid & 3;   // reduce: batch, gate chunk

    int buf = 0;
    for (int s = 0; s < SEQ_LEN; ++s) {
        const int t = dir ? (SEQ_LEN - 1 - s) : s;

        // ---- gx prefetch (independent of the barrier): this thread later
        //      reduces (b=gb, cols gq*8..gq*8+7) -> load matching table chunk.
        long long tok;
        if (tok64) tok = ((const long long*)tokens_raw)[(size_t)t * BATCHSZ + gb];
        else       tok = (long long)((const int*)tokens_raw)[(size_t)t * BATCHSZ + gb];
        const float* gp = table + (size_t)tok * GWID + gq * HIDDEN + K0;
        float4 gx0 = *(const float4*)gp;
        float4 gx1 = *(const float4*)(gp + 4);

        // ---- grid barrier: all CTAs finished writing h(s-1)
        __syncthreads();
        if (tid == 0) {
            __threadfence();
            atomicAdd(&g_bar[s], 1u);
            while (*(volatile unsigned*)&g_bar[s] < (unsigned)gridDim.x) { }
            __threadfence();
        }
        __syncthreads();

        // ---- stage h (this warp's 128 r-rows) via L2 (other SMs wrote it)
        {
            const float4* src = (const float4*)(buf ? hb1 : hb0) + w * 1024;
            float4* dst = (float4*)hs + w * 1024;
#pragma unroll
            for (int i = 0; i < 32; ++i)
                dst[i * 32 + l] = __ldcg(src + i * 32 + l);
        }
        __syncwarp();

        // ---- FFMA2 core: acc2[batch-pair][col] over this warp's 128 r
        u64 acc2[4][4];
#pragma unroll
        for (int p = 0; p < 4; ++p)
#pragma unroll
            for (int j = 0; j < 4; ++j) acc2[p][j] = 0ull;
        {
            const float* hrow = hs + (w << 12) + bg * 8;
            const float* wrow = ws + (w << 12) + cg * 4;
#pragma unroll 4
            for (int r = 0; r < 128; ++r) {
                u64 hp[4];
                hp[0] = *(const u64*)(hrow + 0);   // batches 0,1
                hp[1] = *(const u64*)(hrow + 2);   // batches 2,3
                hp[2] = *(const u64*)(hrow + 4);   // batches 4,5
                hp[3] = *(const u64*)(hrow + 6);   // batches 6,7
                float4 wv = *(const float4*)(wrow);
                u64 w2[4];
                SPLAT2(w2[0], wv.x); SPLAT2(w2[1], wv.y);
                SPLAT2(w2[2], wv.z); SPLAT2(w2[3], wv.w);
#pragma unroll
                for (int p = 0; p < 4; ++p)
#pragma unroll
                    for (int j = 0; j < 4; ++j)
                        FMA2(acc2[p][j], hp[p], w2[j], acc2[p][j]);
                hrow += 32; wrow += 32;
            }
        }
        // ---- store partials: red[w][b][c]
#pragma unroll
        for (int p = 0; p < 4; ++p) {
            float lo[4], hi[4];
#pragma unroll
            for (int j = 0; j < 4; ++j) UNPK2(lo[j], hi[j], acc2[p][j]);
            *(float4*)(red + ((w * 32 + bg * 8 + 2 * p)     * 36 + cg * 4))
                = make_float4(lo[0], lo[1], lo[2], lo[3]);
            *(float4*)(red + ((w * 32 + bg * 8 + 2 * p + 1) * 36 + cg * 4))
                = make_float4(hi[0], hi[1], hi[2], hi[3]);
        }
        __syncthreads();

        // ---- reduce 4 warps + gx -> gates
        {
            float gx[8] = { gx0.x, gx0.y, gx0.z, gx0.w, gx1.x, gx1.y, gx1.z, gx1.w };
#pragma unroll
            for (int cc = 0; cc < 8; ++cc) {
                int c = gq * 8 + cc;
                float v = red[(0 * 32 + gb) * 36 + c] + red[(1 * 32 + gb) * 36 + c]
                        + red[(2 * 32 + gb) * 36 + c] + red[(3 * 32 + gb) * 36 + c]
                        + gx[cc];
                gbuf[gb * 36 + c] = v;
            }
        }
        __syncthreads();

        // ---- LSTM cell (256 cells, 2 per thread), write h to other phase buf
        float* hdst = buf ? hb0 : hb1;
#pragma unroll
        for (int rep = 0; rep < 2; ++rep) {
            int id = tid + rep * 128;
            int j = id >> 5, b = id & 31;
            float ig = gbuf[b * 36 + j];
            float fg = gbuf[b * 36 + 8 + j];
            float gg = gbuf[b * 36 + 16 + j];
            float og = gbuf[b * 36 + 24 + j];
            float iv = 1.0f / (1.0f + __expf(-ig));
            float fv = 1.0f / (1.0f + __expf(-fg));
            float ov = 1.0f / (1.0f + __expf(-og));
            float gv = tanhf(gg);
            float c2 = fv * cs[j * 33 + b] + iv * gv;
            cs[j * 33 + b] = c2;
            float h2 = ov * tanhf(c2);
            hdst[(K0 + j) * BATCHSZ + b] = h2;     // coalesced over b
            hout[b * 8 + j] = h2;
        }
        __syncthreads();

        // ---- output write: out[b][t*1024 + dir*512 + K0 + 0..7]
        if (tid < 64) {
            int b = tid >> 1, half = tid & 1;
            float4 v = *(float4*)(hout + b * 8 + half * 4);
            *(float4*)(out + (size_t)b * (SEQ_LEN * 1024)
                           + (size_t)t * 1024 + dir * 512 + K0 + half * 4) = v;
        }
        buf ^= 1;
    }
}

// ---------------- launch ------------------------------------------------------
extern "C" void kernel_launch(void* const* d_in, const int* in_sizes, int n_in,
                              void* d_out, int out_size)
{
    const void*  tokens = d_in[0];
    const float* h0     = (const float*)d_in[1];
    const float* emb    = (const float*)d_in[2];
    const float* wx_f   = (const float*)d_in[3];
    const float* bx_f   = (const float*)d_in[4];
    const float* wh_f   = (const float*)d_in[5];
    const float* bh_f   = (const float*)d_in[6];
    const float* wx_b   = (const float*)d_in[7];
    const float* bx_b   = (const float*)d_in[8];
    const float* wh_b   = (const float*)d_in[9];
    const float* bh_b   = (const float*)d_in[10];
    float* out = (float*)d_out;

    cudaFuncSetAttribute(rnn_kernel, cudaFuncAttributeMaxDynamicSharedMemorySize,
                         SM_FLOATS * (int)sizeof(float));

    // 1) vocab gate table (parallel GEMM)
    dim3 gg(GWID / 64, VOCAB / 128, 2);
    gx_gemm_kernel<<<gg, 256>>>(emb, wx_f, bx_f, bh_f, wx_b, bx_b, bh_b);

    // 2) reset barriers, seed h, detect token dtype
    init_kernel<<<128, 256>>>((const int*)tokens, h0);

    // 3) persistent recurrence (both directions concurrently)
    rnn_kernel<<<NCTA, 128, SM_FLOATS * (int)sizeof(float)>>>(
        tokens, h0, wh_f, wh_b, out);
}

// round 15
// speedup vs baseline: 1.1719x; 1.1564x over previous
#include <cuda_runtime.h>
#include <cstdint>
#include <cstdio>

#define SEQ_LEN 2048
#define BATCHSZ 32
#define HIDDEN  512
#define VOCAB   32000
#define GWID    2048   /* 4*HIDDEN */
#define NCTA    128    /* 64 CTAs per direction */

typedef unsigned long long u64;

// packed fp32x2 FMA (sm_100+): d = a*b + c on both lanes
#define FMA2(d, a, b, c) \
    asm("fma.rn.f32x2 %0, %1, %2, %3;" : "=l"(d) : "l"(a), "l"(b), "l"(c))
#define SPLAT2(d, f) \
    asm("mov.b64 %0, {%1, %1};" : "=l"(d) : "f"(f))
#define UNPK2(lo, hi, d) \
    asm("mov.b64 {%0, %1}, %2;" : "=f"(lo), "=f"(hi) : "l"(d))

#define CPASYNC16(dst_u32, src_ptr) \
    asm volatile("cp.async.cg.shared.global [%0], [%1], 16;" :: "r"(dst_u32), "l"(src_ptr))
#define CPCOMMIT() asm volatile("cp.async.commit_group;")
#define CPWAIT(n)  asm volatile("cp.async.wait_group %0;" :: "n"(n))

// ---------------- device scratch (static allocation: allowed) ----------------
__device__ float    g_table[(size_t)2 * VOCAB * GWID];   // 524 MB gate bias table
__device__ float    g_hbuf[2][2][HIDDEN * BATCHSZ];      // [dir][phase][r*32+b]
__device__ unsigned g_bar[2][SEQ_LEN];                   // per-dir per-step barriers
__device__ int      g_tok64;

// ---------------- init ---------------------------------------------------------
__global__ void init_kernel(const int* __restrict__ tok32, const float* __restrict__ h0) {
    int i = blockIdx.x * blockDim.x + threadIdx.x;
    if (i < 2 * SEQ_LEN) ((unsigned*)g_bar)[i] = 0;
    if (i < 2 * HIDDEN * BATCHSZ) {
        int d  = i >> 14;
        int rb = i & 16383;
        int b  = rb & 31;
        int r  = rb >> 5;
        g_hbuf[d][0][rb] = h0[b * HIDDEN + r];
    }
    if (i == 0) {
        int nz = 0;
        for (int j = 0; j < 128; ++j) nz |= tok32[2 * j + 1];
        g_tok64 = (nz == 0) ? 1 : 0;
    }
}

// ---------------- vocab gate-table GEMM: 128x128 tile, K16, double-buffered -----
__global__ void __launch_bounds__(256, 2) gx_gemm_kernel(
    const float* __restrict__ E,
    const float* __restrict__ wx_f, const float* __restrict__ bx_f, const float* __restrict__ bh_f,
    const float* __restrict__ wx_b, const float* __restrict__ bx_b, const float* __restrict__ bh_b)
{
    const int d  = blockIdx.z;
    const float* Wx = d ? wx_b : wx_f;
    const float* bx = d ? bx_b : bx_f;
    const float* bh = d ? bh_b : bh_f;
    const int c0 = blockIdx.x * 128;
    const int v0 = blockIdx.y * 128;

    __shared__ float As[2][16][132];   // [k][row] transposed, padded
    __shared__ float Bs[2][16][128];   // [k][c]

    const int tid = threadIdx.x;
    const int tx  = tid & 15;          // cols tx*8..tx*8+8
    const int ty  = tid >> 4;          // rows ty*8..ty*8+8

    u64 acc2[4][8];                    // row-pair p (rows ty*8+2p,+1) x col j
#pragma unroll
    for (int p = 0; p < 4; ++p)
#pragma unroll
        for (int j = 0; j < 8; ++j) acc2[p][j] = 0ull;

    // ---- load helpers (regs) ----
    float4 aR[2], bR[2];
    const int arow0 = tid >> 2;        // + 64*i
    const int akq   = tid & 3;
    const int bk0   = tid >> 5;        // + 8*i
    const int bcq   = tid & 31;

#define GEMM_LDG(KK)                                                        \
    {                                                                       \
        aR[0] = *(const float4*)(E + (size_t)(v0 + arow0)      * HIDDEN + (KK) + akq * 4); \
        aR[1] = *(const float4*)(E + (size_t)(v0 + arow0 + 64) * HIDDEN + (KK) + akq * 4); \
        bR[0] = *(const float4*)(Wx + (size_t)((KK) + bk0)     * GWID + c0 + bcq * 4);     \
        bR[1] = *(const float4*)(Wx + (size_t)((KK) + bk0 + 8) * GWID + c0 + bcq * 4);     \
    }
#define GEMM_STS(BUF)                                                       \
    {                                                                       \
        As[BUF][akq * 4 + 0][arow0]      = aR[0].x;                         \
        As[BUF][akq * 4 + 1][arow0]      = aR[0].y;                         \
        As[BUF][akq * 4 + 2][arow0]      = aR[0].z;                         \
        As[BUF][akq * 4 + 3][arow0]      = aR[0].w;                         \
        As[BUF][akq * 4 + 0][arow0 + 64] = aR[1].x;                         \
        As[BUF][akq * 4 + 1][arow0 + 64] = aR[1].y;                         \
        As[BUF][akq * 4 + 2][arow0 + 64] = aR[1].z;                         \
        As[BUF][akq * 4 + 3][arow0 + 64] = aR[1].w;                         \
        *(float4*)&Bs[BUF][bk0][bcq * 4]     = bR[0];                       \
        *(float4*)&Bs[BUF][bk0 + 8][bcq * 4] = bR[1];                       \
    }

    GEMM_LDG(0);
    GEMM_STS(0);
    __syncthreads();

    for (int ch = 0; ch < 32; ++ch) {
        const int cur = ch & 1;
        if (ch + 1 < 32) GEMM_LDG((ch + 1) * 16);
#pragma unroll
        for (int k = 0; k < 16; ++k) {
            const float* ap = &As[cur][k][ty * 8];
            u64 a2[4];
            a2[0] = *(const u64*)(ap + 0);
            a2[1] = *(const u64*)(ap + 2);
            a2[2] = *(const u64*)(ap + 4);
            a2[3] = *(const u64*)(ap + 6);
            float b8[8];
            *(float4*)&b8[0] = *(const float4*)&Bs[cur][k][tx * 8];
            *(float4*)&b8[4] = *(const float4*)&Bs[cur][k][tx * 8 + 4];
            u64 w2[8];
#pragma unroll
            for (int j = 0; j < 8; ++j) SPLAT2(w2[j], b8[j]);
#pragma unroll
            for (int p = 0; p < 4; ++p)
#pragma unroll
                for (int j = 0; j < 8; ++j)
                    FMA2(acc2[p][j], a2[p], w2[j], acc2[p][j]);
        }
        if (ch + 1 < 32) GEMM_STS(cur ^ 1);
        __syncthreads();
    }

    // ---- epilogue: add bias, store two rows per pair ----
    float bias[8];
    {
        float4 x0 = *(const float4*)(bx + c0 + tx * 8);
        float4 x1 = *(const float4*)(bx + c0 + tx * 8 + 4);
        float4 h0v = *(const float4*)(bh + c0 + tx * 8);
        float4 h1v = *(const float4*)(bh + c0 + tx * 8 + 4);
        bias[0] = x0.x + h0v.x; bias[1] = x0.y + h0v.y;
        bias[2] = x0.z + h0v.z; bias[3] = x0.w + h0v.w;
        bias[4] = x1.x + h1v.x; bias[5] = x1.y + h1v.y;
        bias[6] = x1.z + h1v.z; bias[7] = x1.w + h1v.w;
    }
    float* Cbase = g_table + (size_t)d * VOCAB * GWID;
#pragma unroll
    for (int p = 0; p < 4; ++p) {
        float lo[8], hi[8];
#pragma unroll
        for (int j = 0; j < 8; ++j) UNPK2(lo[j], hi[j], acc2[p][j]);
        size_t r0 = (size_t)(v0 + ty * 8 + 2 * p) * GWID + c0 + tx * 8;
        float4 o;
        o = make_float4(lo[0]+bias[0], lo[1]+bias[1], lo[2]+bias[2], lo[3]+bias[3]);
        *(float4*)(Cbase + r0) = o;
        o = make_float4(lo[4]+bias[4], lo[5]+bias[5], lo[6]+bias[6], lo[7]+bias[7]);
        *(float4*)(Cbase + r0 + 4) = o;
        o = make_float4(hi[0]+bias[0], hi[1]+bias[1], hi[2]+bias[2], hi[3]+bias[3]);
        *(float4*)(Cbase + r0 + GWID) = o;
        o = make_float4(hi[4]+bias[4], hi[5]+bias[5], hi[6]+bias[6], hi[7]+bias[7]);
        *(float4*)(Cbase + r0 + GWID + 4) = o;
    }
}

// ---------------- persistent bidirectional LSTM recurrence ---------------------
// 128 CTAs x 256 threads (8 warps). CTA: dir = bid>>6, hidden units K0..K0+7.
#define SM_WS   0
#define SM_HS   16384
#define SM_RED  32768                  /* [8][32][36] = 9216 */
#define SM_GB   (SM_RED + 8*32*36)     /* [32][36]  = 1152  */
#define SM_CS   (SM_GB + 32*36)        /* [8][33]   = 264   */
#define SM_HOUT (SM_CS + 8*33)         /* [32][8]   = 256   */
#define SM_FLOATS (SM_HOUT + 32*8)     /* 43656 floats = 174624 B */

__global__ void __launch_bounds__(256, 1) rnn_kernel(
    const void* __restrict__ tokens_raw,
    const float* __restrict__ h0,
    const float* __restrict__ wh_f,
    const float* __restrict__ wh_b,
    float* __restrict__ out)
{
    extern __shared__ float smem[];
    float* ws   = smem + SM_WS;
    float* hs   = smem + SM_HS;
    float* red  = smem + SM_RED;
    float* gbuf = smem + SM_GB;
    float* cs   = smem + SM_CS;
    float* hout = smem + SM_HOUT;

    const int tid = threadIdx.x;
    const int dir = blockIdx.x >> 6;
    const int K0  = (blockIdx.x & 63) * 8;
    const float* wh = dir ? wh_b : wh_f;

    // wh slice: ws[r*32 + g*8 + j] = wh[r][g*512 + K0 + j]
    for (int i = tid; i < 16384; i += 256) {
        int r = i >> 5, c = i & 31;
        int g = c >> 3, j = c & 7;
        ws[i] = wh[(size_t)r * GWID + g * HIDDEN + K0 + j];
    }
    {   // cell state init: c0 = h0
        int j = tid >> 5, b = tid & 31;
        cs[j * 33 + b] = h0[b * HIDDEN + K0 + j];
    }
    __syncthreads();

    const int tok64 = g_tok64;
    const float* table = g_table + (size_t)dir * VOCAB * GWID;
    float* hb0 = &g_hbuf[dir][0][0];
    float* hb1 = &g_hbuf[dir][1][0];
    unsigned* bar = &g_bar[dir][0];
    const uint32_t hs_u32 = (uint32_t)__cvta_generic_to_shared(hs);

    const int w  = tid >> 5, l = tid & 31;   // warp (r-range w*64..+64), lane
    const int bg = l & 3,  cg = l >> 2;      // batches bg*8..+8, cols cg*4..+4
    const int rb = tid >> 3, rq = tid & 7;   // reduce: batch rb, col chunk rq*4
    const int rg = rq >> 1, rj0 = (rq & 1) * 4; // gate idx / col offset for gx fetch

    int buf = 0;
    for (int s = 0; s < SEQ_LEN; ++s) {
        const int t = dir ? (SEQ_LEN - 1 - s) : s;

        // ---- gx prefetch (independent of barrier)
        long long tok;
        if (tok64) tok = ((const long long*)tokens_raw)[(size_t)t * BATCHSZ + rb];
        else       tok = (long long)((const int*)tokens_raw)[(size_t)t * BATCHSZ + rb];
        float4 gxv = *(const float4*)(table + (size_t)tok * GWID + rg * HIDDEN + K0 + rj0);

        // ---- barrier arrival (tid0) overlapped with prev-step out-write
        //      (writer set tid 64..127 is DISJOINT from the barrier thread!)
        __syncthreads();                 // prev cell writes done CTA-wide
        if (tid == 0) {
            __threadfence();
            atomicAdd(&bar[s], 1u);
            while (*(volatile unsigned*)&bar[s] < 64u) { }
            __threadfence();
        } else if (tid >= 64 && tid < 128 && s > 0) {
            const int tp = dir ? (SEQ_LEN - s) : (s - 1);
            int q = tid - 64;
            int b2 = q >> 1, half = q & 1;
            float4 v = *(float4*)(hout + b2 * 8 + half * 4);
            *(float4*)(out + (size_t)b2 * (SEQ_LEN * 1024)
                           + (size_t)tp * 1024 + dir * 512 + K0 + half * 4) = v;
        }
        __syncthreads();

        // ---- pipelined h stage (cp.async, 4 groups of 16 r) + FMA
        {
            const float4* src4 = (const float4*)(buf ? hb1 : hb0) + (w << 9);
            const uint32_t dst0 = hs_u32 + ((w << 9) << 4);
#pragma unroll
            for (int g = 0; g < 4; ++g) {
#pragma unroll
                for (int ii = 0; ii < 4; ++ii) {
                    int idx = (g * 4 + ii) * 32 + l;
                    CPASYNC16(dst0 + idx * 16, src4 + idx);
                }
                CPCOMMIT();
            }
        }

        u64 acc2[4][4];
#pragma unroll
        for (int p = 0; p < 4; ++p)
#pragma unroll
            for (int j = 0; j < 4; ++j) acc2[p][j] = 0ull;

#define FMA_CHUNK(R0)                                                        \
        {                                                                    \
            const float* hrow = hs + (w << 11) + (R0) * 32 + bg * 8;         \
            const float* wrow = ws + (w << 11) + (R0) * 32 + cg * 4;         \
            _Pragma("unroll 4")                                              \
            for (int r = 0; r < 16; ++r) {                                   \
                u64 hp[4];                                                   \
                hp[0] = *(const u64*)(hrow + 0);                             \
                hp[1] = *(const u64*)(hrow + 2);                             \
                hp[2] = *(const u64*)(hrow + 4);                             \
                hp[3] = *(const u64*)(hrow + 6);                             \
                float4 wv = *(const float4*)(wrow);                          \
                u64 w2[4];                                                   \
                SPLAT2(w2[0], wv.x); SPLAT2(w2[1], wv.y);                    \
                SPLAT2(w2[2], wv.z); SPLAT2(w2[3], wv.w);                    \
                _Pragma("unroll")                                            \
                for (int p = 0; p < 4; ++p)                                  \
                    _Pragma("unroll")                                        \
                    for (int j = 0; j < 4; ++j)                              \
                        FMA2(acc2[p][j], hp[p], w2[j], acc2[p][j]);          \
                hrow += 32; wrow += 32;                                      \
            }                                                                \
        }

        CPWAIT(3); __syncwarp(); FMA_CHUNK(0);
        CPWAIT(2); __syncwarp(); FMA_CHUNK(16);
        CPWAIT(1); __syncwarp(); FMA_CHUNK(32);
        CPWAIT(0); __syncwarp(); FMA_CHUNK(48);

        // ---- store partials: red[(w*32 + b)*36 + c]
#pragma unroll
        for (int p = 0; p < 4; ++p) {
            float lo[4], hi[4];
#pragma unroll
            for (int j = 0; j < 4; ++j) UNPK2(lo[j], hi[j], acc2[p][j]);
            *(float4*)(red + ((w * 32 + bg * 8 + 2 * p)     * 36 + cg * 4))
                = make_float4(lo[0], lo[1], lo[2], lo[3]);
            *(float4*)(red + ((w * 32 + bg * 8 + 2 * p + 1) * 36 + cg * 4))
                = make_float4(hi[0], hi[1], hi[2], hi[3]);
        }
        __syncthreads();

        // ---- reduce 8 warps + gx -> gates (256 threads, 4 cols each)
        {
            float4 sum = gxv;
#pragma unroll
            for (int w8 = 0; w8 < 8; ++w8) {
                float4 v = *(const float4*)(red + (w8 * 32 + rb) * 36 + rq * 4);
                sum.x += v.x; sum.y += v.y; sum.z += v.z; sum.w += v.w;
            }
            *(float4*)(gbuf + rb * 36 + rq * 4) = sum;
        }
        __syncthreads();

        // ---- LSTM cell (256 cells, 1 per thread)
        {
            float* hdst = buf ? hb0 : hb1;
            int j = tid >> 5, b = tid & 31;
            float ig = gbuf[b * 36 + j];
            float fg = gbuf[b * 36 + 8 + j];
            float gg = gbuf[b * 36 + 16 + j];
            float og = gbuf[b * 36 + 24 + j];
            float iv = 1.0f / (1.0f + __expf(-ig));
            float fv = 1.0f / (1.0f + __expf(-fg));
            float ov = 1.0f / (1.0f + __expf(-og));
            float gv = tanhf(gg);
            float c2 = fv * cs[j * 33 + b] + iv * gv;
            cs[j * 33 + b] = c2;
            float h2 = ov * tanhf(c2);
            hdst[(K0 + j) * BATCHSZ + b] = h2;
            hout[b * 8 + j] = h2;
        }
        buf ^= 1;
    }

    // ---- final step's output write
    __syncthreads();
    if (tid < 64) {
        const int tl = dir ? 0 : (SEQ_LEN - 1);
        int b2 = tid >> 1, half = tid & 1;
        float4 v = *(float4*)(hout + b2 * 8 + half * 4);
        *(float4*)(out + (size_t)b2 * (SEQ_LEN * 1024)
                       + (size_t)tl * 1024 + dir * 512 + K0 + half * 4) = v;
    }
}

// ---------------- launch --------------------------------------------------------
extern "C" void kernel_launch(void* const* d_in, const int* in_sizes, int n_in,
                              void* d_out, int out_size)
{
    const void*  tokens = d_in[0];
    const float* h0     = (const float*)d_in[1];
    const float* emb    = (const float*)d_in[2];
    const float* wx_f   = (const float*)d_in[3];
    const float* bx_f   = (const float*)d_in[4];
    const float* wh_f   = (const float*)d_in[5];
    const float* bh_f   = (const float*)d_in[6];
    const float* wx_b   = (const float*)d_in[7];
    const float* bx_b   = (const float*)d_in[8];
    const float* wh_b   = (const float*)d_in[9];
    const float* bh_b   = (const float*)d_in[10];
    float* out = (float*)d_out;

    cudaFuncSetAttribute(rnn_kernel, cudaFuncAttributeMaxDynamicSharedMemorySize,
                         SM_FLOATS * (int)sizeof(float));

    // 1) vocab gate table (parallel GEMM, 128x128 tiles)
    dim3 gg(GWID / 128, VOCAB / 128, 2);
    gx_gemm_kernel<<<gg, 256>>>(emb, wx_f, bx_f, bh_f, wx_b, bx_b, bh_b);

    // 2) reset barriers, seed h, detect token dtype
    init_kernel<<<128, 256>>>((const int*)tokens, h0);

    // 3) persistent recurrence
    rnn_kernel<<<NCTA, 256, SM_FLOATS * (int)sizeof(float)>>>(
        tokens, h0, wh_f, wh_b, out);
}

// round 16
// speedup vs baseline: 1.2619x; 1.0768x over previous
#include <cuda_runtime.h>
#include <cstdint>
#include <cstdio>

#define SEQ_LEN 2048
#define BATCHSZ 32
#define HIDDEN  512
#define VOCAB   32000
#define GWID    2048   /* 4*HIDDEN */
#define NCTA    128    /* 64 CTAs per direction */

typedef unsigned long long u64;

// packed fp32x2 FMA (sm_100+): d = a*b + c on both lanes
#define FMA2(d, a, b, c) \
    asm("fma.rn.f32x2 %0, %1, %2, %3;" : "=l"(d) : "l"(a), "l"(b), "l"(c))
#define SPLAT2(d, f) \
    asm("mov.b64 %0, {%1, %1};" : "=l"(d) : "f"(f))
#define UNPK2(lo, hi, d) \
    asm("mov.b64 {%0, %1}, %2;" : "=f"(lo), "=f"(hi) : "l"(d))

#define CPASYNC16(dst_u32, src_ptr) \
    asm volatile("cp.async.cg.shared.global [%0], [%1], 16;" :: "r"(dst_u32), "l"(src_ptr))
#define CPCOMMIT() asm volatile("cp.async.commit_group;")
#define CPWAIT(n)  asm volatile("cp.async.wait_group %0;" :: "n"(n))

// ---------------- device scratch (static allocation: allowed) ----------------
__device__ float    g_table[(size_t)2 * VOCAB * GWID];   // 524 MB gate bias table
__device__ float    g_hbuf[2][2][HIDDEN * BATCHSZ];      // [dir][phase][r*32+b]
__device__ unsigned g_prog[2][64][32];                   // per-CTA progress (128B stride)
__device__ int      g_tok64;

// ---------------- init ---------------------------------------------------------
__global__ void init_kernel(const int* __restrict__ tok32, const float* __restrict__ h0) {
    int i = blockIdx.x * blockDim.x + threadIdx.x;
    if (i < 2 * 64 * 32) ((unsigned*)g_prog)[i] = 0;
    if (i < 2 * HIDDEN * BATCHSZ) {
        int d  = i >> 14;
        int rb = i & 16383;
        int b  = rb & 31;
        int r  = rb >> 5;
        g_hbuf[d][0][rb] = h0[b * HIDDEN + r];
    }
    if (i == 0) {
        int nz = 0;
        for (int j = 0; j < 128; ++j) nz |= tok32[2 * j + 1];
        g_tok64 = (nz == 0) ? 1 : 0;
    }
}

// ---------------- vocab gate-table GEMM: 128x128 tile, K16, double-buffered -----
__global__ void __launch_bounds__(256, 2) gx_gemm_kernel(
    const float* __restrict__ E,
    const float* __restrict__ wx_f, const float* __restrict__ bx_f, const float* __restrict__ bh_f,
    const float* __restrict__ wx_b, const float* __restrict__ bx_b, const float* __restrict__ bh_b)
{
    const int d  = blockIdx.z;
    const float* Wx = d ? wx_b : wx_f;
    const float* bx = d ? bx_b : bx_f;
    const float* bh = d ? bh_b : bh_f;
    const int c0 = blockIdx.x * 128;
    const int v0 = blockIdx.y * 128;

    __shared__ float As[2][16][132];   // [k][row] transposed, padded
    __shared__ float Bs[2][16][128];   // [k][c]

    const int tid = threadIdx.x;
    const int tx  = tid & 15;          // cols tx*8..tx*8+8
    const int ty  = tid >> 4;          // rows ty*8..ty*8+8

    u64 acc2[4][8];                    // row-pair p x col j
#pragma unroll
    for (int p = 0; p < 4; ++p)
#pragma unroll
        for (int j = 0; j < 8; ++j) acc2[p][j] = 0ull;

    float4 aR[2], bR[2];
    const int arow0 = tid >> 2;        // + 64*i
    const int akq   = tid & 3;
    const int bk0   = tid >> 5;        // + 8*i
    const int bcq   = tid & 31;

#define GEMM_LDG(KK)                                                        \
    {                                                                       \
        aR[0] = *(const float4*)(E + (size_t)(v0 + arow0)      * HIDDEN + (KK) + akq * 4); \
        aR[1] = *(const float4*)(E + (size_t)(v0 + arow0 + 64) * HIDDEN + (KK) + akq * 4); \
        bR[0] = *(const float4*)(Wx + (size_t)((KK) + bk0)     * GWID + c0 + bcq * 4);     \
        bR[1] = *(const float4*)(Wx + (size_t)((KK) + bk0 + 8) * GWID + c0 + bcq * 4);     \
    }
#define GEMM_STS(BUF)                                                       \
    {                                                                       \
        As[BUF][akq * 4 + 0][arow0]      = aR[0].x;                         \
        As[BUF][akq * 4 + 1][arow0]      = aR[0].y;                         \
        As[BUF][akq * 4 + 2][arow0]      = aR[0].z;                         \
        As[BUF][akq * 4 + 3][arow0]      = aR[0].w;                         \
        As[BUF][akq * 4 + 0][arow0 + 64] = aR[1].x;                         \
        As[BUF][akq * 4 + 1][arow0 + 64] = aR[1].y;                         \
        As[BUF][akq * 4 + 2][arow0 + 64] = aR[1].z;                         \
        As[BUF][akq * 4 + 3][arow0 + 64] = aR[1].w;                         \
        *(float4*)&Bs[BUF][bk0][bcq * 4]     = bR[0];                       \
        *(float4*)&Bs[BUF][bk0 + 8][bcq * 4] = bR[1];                       \
    }

    GEMM_LDG(0);
    GEMM_STS(0);
    __syncthreads();

    for (int ch = 0; ch < 32; ++ch) {
        const int cur = ch & 1;
        if (ch + 1 < 32) GEMM_LDG((ch + 1) * 16);
#pragma unroll
        for (int k = 0; k < 16; ++k) {
            const float* ap = &As[cur][k][ty * 8];
            u64 a2[4];
            a2[0] = *(const u64*)(ap + 0);
            a2[1] = *(const u64*)(ap + 2);
            a2[2] = *(const u64*)(ap + 4);
            a2[3] = *(const u64*)(ap + 6);
            float b8[8];
            *(float4*)&b8[0] = *(const float4*)&Bs[cur][k][tx * 8];
            *(float4*)&b8[4] = *(const float4*)&Bs[cur][k][tx * 8 + 4];
            u64 w2[8];
#pragma unroll
            for (int j = 0; j < 8; ++j) SPLAT2(w2[j], b8[j]);
#pragma unroll
            for (int p = 0; p < 4; ++p)
#pragma unroll
                for (int j = 0; j < 8; ++j)
                    FMA2(acc2[p][j], a2[p], w2[j], acc2[p][j]);
        }
        if (ch + 1 < 32) GEMM_STS(cur ^ 1);
        __syncthreads();
    }

    float bias[8];
    {
        float4 x0 = *(const float4*)(bx + c0 + tx * 8);
        float4 x1 = *(const float4*)(bx + c0 + tx * 8 + 4);
        float4 h0v = *(const float4*)(bh + c0 + tx * 8);
        float4 h1v = *(const float4*)(bh + c0 + tx * 8 + 4);
        bias[0] = x0.x + h0v.x; bias[1] = x0.y + h0v.y;
        bias[2] = x0.z + h0v.z; bias[3] = x0.w + h0v.w;
        bias[4] = x1.x + h1v.x; bias[5] = x1.y + h1v.y;
        bias[6] = x1.z + h1v.z; bias[7] = x1.w + h1v.w;
    }
    float* Cbase = g_table + (size_t)d * VOCAB * GWID;
#pragma unroll
    for (int p = 0; p < 4; ++p) {
        float lo[8], hi[8];
#pragma unroll
        for (int j = 0; j < 8; ++j) UNPK2(lo[j], hi[j], acc2[p][j]);
        size_t r0 = (size_t)(v0 + ty * 8 + 2 * p) * GWID + c0 + tx * 8;
        float4 o;
        o = make_float4(lo[0]+bias[0], lo[1]+bias[1], lo[2]+bias[2], lo[3]+bias[3]);
        *(float4*)(Cbase + r0) = o;
        o = make_float4(lo[4]+bias[4], lo[5]+bias[5], lo[6]+bias[6], lo[7]+bias[7]);
        *(float4*)(Cbase + r0 + 4) = o;
        o = make_float4(hi[0]+bias[0], hi[1]+bias[1], hi[2]+bias[2], hi[3]+bias[3]);
        *(float4*)(Cbase + r0 + GWID) = o;
        o = make_float4(hi[4]+bias[4], hi[5]+bias[5], hi[6]+bias[6], hi[7]+bias[7]);
        *(float4*)(Cbase + r0 + GWID + 4) = o;
    }
}

// ---------------- persistent bidirectional LSTM recurrence ---------------------
// 128 CTAs x 256 threads (8 warps). CTA: dir = bid>>6, hidden units K0..K0+7.
// Decentralized sync: per-CTA progress counters; warp w waits only on the
// producers (CTAs 8w..8w+7) of its 64 h-rows, 2 CTAs per 16-row chunk.
#define SM_WS   0
#define SM_HS   16384
#define SM_RED  32768                  /* [8][32][36] = 9216 */
#define SM_GB   (SM_RED + 8*32*36)     /* [32][36]  = 1152  */
#define SM_CS   (SM_GB + 32*36)        /* [8][33]   = 264   */
#define SM_HOUT (SM_CS + 8*33)         /* [32][8]   = 256   */
#define SM_FLOATS (SM_HOUT + 32*8)     /* 43656 floats = 174624 B */

__global__ void __launch_bounds__(256, 1) rnn_kernel(
    const void* __restrict__ tokens_raw,
    const float* __restrict__ h0,
    const float* __restrict__ wh_f,
    const float* __restrict__ wh_b,
    float* __restrict__ out)
{
    extern __shared__ float smem[];
    float* ws   = smem + SM_WS;
    float* hs   = smem + SM_HS;
    float* red  = smem + SM_RED;
    float* gbuf = smem + SM_GB;
    float* cs   = smem + SM_CS;
    float* hout = smem + SM_HOUT;

    const int tid = threadIdx.x;
    const int dir = blockIdx.x >> 6;
    const int myCta = blockIdx.x & 63;
    const int K0  = myCta * 8;
    const float* wh = dir ? wh_b : wh_f;

    // wh slice: ws[r*32 + g*8 + j] = wh[r][g*512 + K0 + j]
    for (int i = tid; i < 16384; i += 256) {
        int r = i >> 5, c = i & 31;
        int g = c >> 3, j = c & 7;
        ws[i] = wh[(size_t)r * GWID + g * HIDDEN + K0 + j];
    }
    {   // cell state init: c0 = h0
        int j = tid >> 5, b = tid & 31;
        cs[j * 33 + b] = h0[b * HIDDEN + K0 + j];
    }
    __syncthreads();

    const int tok64 = g_tok64;
    const float* table = g_table + (size_t)dir * VOCAB * GWID;
    float* hb0 = &g_hbuf[dir][0][0];
    float* hb1 = &g_hbuf[dir][1][0];
    volatile unsigned* prog = &g_prog[dir][0][0];   // stride 32 u32 per CTA
    const uint32_t hs_u32 = (uint32_t)__cvta_generic_to_shared(hs);

    const int w  = tid >> 5, l = tid & 31;   // warp (rows 64w..64w+63), lane
    const int bg = l & 3,  cg = l >> 2;      // batches bg*8..+8, cols cg*4..+4
    const int rb = tid >> 3, rq = tid & 7;   // reduce: batch rb, col chunk rq*4
    const int rg = rq >> 1, rj0 = (rq & 1) * 4;

    // lane 0/1 poll CTA (8w + 2g + l) for chunk g
    const int pollBase = 8 * w;

#define POLL_CHUNK(G)                                                        \
    {                                                                        \
        bool rdy;                                                            \
        do {                                                                 \
            rdy = (l < 2) ? (prog[(pollBase + 2*(G) + l) * 32] >= (unsigned)s) : true; \
        } while (!__all_sync(0xffffffffu, rdy));                             \
    }

#define ISSUE_CHUNK(G)                                                       \
    {                                                                        \
        const float4* src4 = hsrc4 + ((G) * 4) * 32;                         \
        const uint32_t dst = dst0 + (((G) * 4) * 32) * 16;                   \
        CPASYNC16(dst + (0 * 32 + l) * 16, src4 + 0 * 32 + l);               \
        CPASYNC16(dst + (1 * 32 + l) * 16, src4 + 1 * 32 + l);               \
        CPASYNC16(dst + (2 * 32 + l) * 16, src4 + 2 * 32 + l);               \
        CPASYNC16(dst + (3 * 32 + l) * 16, src4 + 3 * 32 + l);               \
        CPCOMMIT();                                                          \
    }

#define FMA_CHUNK(R0)                                                        \
        {                                                                    \
            const float* hrow = hs + (w << 11) + (R0) * 32 + bg * 8;         \
            const float* wrow = ws + (w << 11) + (R0) * 32 + cg * 4;         \
            _Pragma("unroll 4")                                              \
            for (int r = 0; r < 16; ++r) {                                   \
                u64 hp[4];                                                   \
                hp[0] = *(const u64*)(hrow + 0);                             \
                hp[1] = *(const u64*)(hrow + 2);                             \
                hp[2] = *(const u64*)(hrow + 4);                             \
                hp[3] = *(const u64*)(hrow + 6);                             \
                float4 wv = *(const float4*)(wrow);                          \
                u64 w2[4];                                                   \
                SPLAT2(w2[0], wv.x); SPLAT2(w2[1], wv.y);                    \
                SPLAT2(w2[2], wv.z); SPLAT2(w2[3], wv.w);                    \
                _Pragma("unroll")                                            \
                for (int p = 0; p < 4; ++p)                                  \
                    _Pragma("unroll")                                        \
                    for (int j = 0; j < 4; ++j)                              \
                        FMA2(acc2[p][j], hp[p], w2[j], acc2[p][j]);          \
                hrow += 32; wrow += 32;                                      \
            }                                                                \
        }

    int buf = 0;
    for (int s = 0; s < SEQ_LEN; ++s) {
        const int t = dir ? (SEQ_LEN - 1 - s) : s;

        // ---- publish h(s-1) completion (all cell STG were before this sync)
        __syncthreads();
        if (tid == 0 && s > 0) {
            __threadfence();
            prog[myCta * 32] = (unsigned)s;
        }
        // ---- prev-step output write (warps 2-3; disjoint from tid 0)
        if (tid >= 64 && tid < 128 && s > 0) {
            const int tp = dir ? (SEQ_LEN - s) : (s - 1);
            int q = tid - 64;
            int b2 = q >> 1, half = q & 1;
            float4 v = *(float4*)(hout + b2 * 8 + half * 4);
            *(float4*)(out + (size_t)b2 * (SEQ_LEN * 1024)
                           + (size_t)tp * 1024 + dir * 512 + K0 + half * 4) = v;
        }

        // ---- gx prefetch (in flight while polling)
        long long tok;
        if (tok64) tok = ((const long long*)tokens_raw)[(size_t)t * BATCHSZ + rb];
        else       tok = (long long)((const int*)tokens_raw)[(size_t)t * BATCHSZ + rb];
        float4 gxv = *(const float4*)(table + (size_t)tok * GWID + rg * HIDDEN + K0 + rj0);

        u64 acc2[4][4];
#pragma unroll
        for (int p = 0; p < 4; ++p)
#pragma unroll
            for (int j = 0; j < 4; ++j) acc2[p][j] = 0ull;

        // ---- per-warp producer-chunk pipeline
        const float4* hsrc4 = (const float4*)(buf ? hb1 : hb0) + (w << 9);
        const uint32_t dst0 = hs_u32 + ((w << 9) << 4);

        POLL_CHUNK(0); ISSUE_CHUNK(0);
        POLL_CHUNK(1); ISSUE_CHUNK(1);
        CPWAIT(1); __syncwarp(); FMA_CHUNK(0);
        POLL_CHUNK(2); ISSUE_CHUNK(2);
        CPWAIT(1); __syncwarp(); FMA_CHUNK(16);
        POLL_CHUNK(3); ISSUE_CHUNK(3);
        CPWAIT(1); __syncwarp(); FMA_CHUNK(32);
        CPWAIT(0); __syncwarp(); FMA_CHUNK(48);

        // ---- store partials: red[(w*32 + b)*36 + c]
#pragma unroll
        for (int p = 0; p < 4; ++p) {
            float lo[4], hi[4];
#pragma unroll
            for (int j = 0; j < 4; ++j) UNPK2(lo[j], hi[j], acc2[p][j]);
            *(float4*)(red + ((w * 32 + bg * 8 + 2 * p)     * 36 + cg * 4))
                = make_float4(lo[0], lo[1], lo[2], lo[3]);
            *(float4*)(red + ((w * 32 + bg * 8 + 2 * p + 1) * 36 + cg * 4))
                = make_float4(hi[0], hi[1], hi[2], hi[3]);
        }
        __syncthreads();

        // ---- reduce 8 warps + gx -> gates
        {
            float4 sum = gxv;
#pragma unroll
            for (int w8 = 0; w8 < 8; ++w8) {
                float4 v = *(const float4*)(red + (w8 * 32 + rb) * 36 + rq * 4);
                sum.x += v.x; sum.y += v.y; sum.z += v.z; sum.w += v.w;
            }
            *(float4*)(gbuf + rb * 36 + rq * 4) = sum;
        }
        __syncthreads();

        // ---- LSTM cell (256 cells, 1 per thread)
        {
            float* hdst = buf ? hb0 : hb1;
            int j = tid >> 5, b = tid & 31;
            float ig = gbuf[b * 36 + j];
            float fg = gbuf[b * 36 + 8 + j];
            float gg = gbuf[b * 36 + 16 + j];
            float og = gbuf[b * 36 + 24 + j];
            float iv = 1.0f / (1.0f + __expf(-ig));
            float fv = 1.0f / (1.0f + __expf(-fg));
            float ov = 1.0f / (1.0f + __expf(-og));
            float gv = tanhf(gg);
            float c2 = fv * cs[j * 33 + b] + iv * gv;
            cs[j * 33 + b] = c2;
            float h2 = ov * tanhf(c2);
            hdst[(K0 + j) * BATCHSZ + b] = h2;
            hout[b * 8 + j] = h2;
        }
        buf ^= 1;
    }

    // ---- final step's output write
    __syncthreads();
    if (tid < 64) {
        const int tl = dir ? 0 : (SEQ_LEN - 1);
        int b2 = tid >> 1, half = tid & 1;
        float4 v = *(float4*)(hout + b2 * 8 + half * 4);
        *(float4*)(out + (size_t)b2 * (SEQ_LEN * 1024)
                       + (size_t)tl * 1024 + dir * 512 + K0 + half * 4) = v;
    }
}

// ---------------- launch --------------------------------------------------------
extern "C" void kernel_launch(void* const* d_in, const int* in_sizes, int n_in,
                              void* d_out, int out_size)
{
    const void*  tokens = d_in[0];
    const float* h0     = (const float*)d_in[1];
    const float* emb    = (const float*)d_in[2];
    const float* wx_f   = (const float*)d_in[3];
    const float* bx_f   = (const float*)d_in[4];
    const float* wh_f   = (const float*)d_in[5];
    const float* bh_f   = (const float*)d_in[6];
    const float* wx_b   = (const float*)d_in[7];
    const float* bx_b   = (const float*)d_in[8];
    const float* wh_b   = (const float*)d_in[9];
    const float* bh_b   = (const float*)d_in[10];
    float* out = (float*)d_out;

    cudaFuncSetAttribute(rnn_kernel, cudaFuncAttributeMaxDynamicSharedMemorySize,
                         SM_FLOATS * (int)sizeof(float));

    // 1) vocab gate table (parallel GEMM, 128x128 tiles)
    dim3 gg(GWID / 128, VOCAB / 128, 2);
    gx_gemm_kernel<<<gg, 256>>>(emb, wx_f, bx_f, bh_f, wx_b, bx_b, bh_b);

    // 2) reset progress counters, seed h, detect token dtype
    init_kernel<<<128, 256>>>((const int*)tokens, h0);

    // 3) persistent recurrence
    rnn_kernel<<<NCTA, 256, SM_FLOATS * (int)sizeof(float)>>>(
        tokens, h0, wh_f, wh_b, out);
}